// round 2
// baseline (speedup 1.0000x reference)
#include <cuda_runtime.h>
#include <math.h>
#include <stdint.h>

#define N0   50000
#define KP1  25000
#define KP2  12500
#define KP3  6250
#define NE   800000
#define CH   256
#define CIN  32
#define PW1  65536
#define PW2  32768
#define PW3  16384

typedef unsigned long long u64;

// ------------------------- scratch (device globals) -------------------------
__device__ int   g_src[NE], g_dst[NE];
__device__ int   g_e1s[NE], g_e1d[NE], g_e2s[NE], g_e2d[NE], g_e3s[NE], g_e3d[NE];
__device__ int   g_es0[NE], g_es1[NE], g_es2[NE], g_es3[NE];
__device__ int   g_rp0[N0+1], g_rp1[KP1+1], g_rp2[KP2+1], g_rp3[KP3+1];
__device__ int   g_cnt[N0+1];
__device__ int   g_m1, g_m2, g_m3, g_flag;
__device__ int   g_map[N0];
__device__ int   g_perm1[KP1], g_perm2[KP2], g_perm3[KP3];
__device__ float g_h0[N0*CH];
__device__ float g_h1[KP1*CH];
__device__ float g_h2[KP2*CH];
__device__ float g_h3[KP3*CH];
__device__ float g_xa[N0*CH];
__device__ float g_xb[KP1*CH];
__device__ float g_agg[N0*CH];
__device__ float g_score[N0];
__device__ u64   g_keys[PW1];
__device__ float g_wnorm;

// ------------------------- small utility kernels ----------------------------
__global__ void k_detect(const unsigned* __restrict__ w) {
    // int64 little-endian: values in [0,50000) => all odd 32-bit words are 0.
    __shared__ int any;
    if (threadIdx.x == 0) any = 0;
    __syncthreads();
    for (int i = threadIdx.x; i < 2048; i += blockDim.x)
        if (w[2*i + 1] != 0u) any = 1;
    __syncthreads();
    if (threadIdx.x == 0) g_flag = (any == 0) ? 1 : 0;
}

__global__ void k_convert(const unsigned* __restrict__ w) {
    int i = blockIdx.x * blockDim.x + threadIdx.x;
    if (i >= NE) return;
    if (g_flag) {  // int64
        g_src[i] = (int)w[2*i];
        g_dst[i] = (int)w[2*(NE + i)];
    } else {       // int32
        const int* p = (const int*)w;
        g_src[i] = p[i];
        g_dst[i] = p[NE + i];
    }
}

__global__ void k_fill_int(int* p, int n, int v) {
    int i = blockIdx.x * blockDim.x + threadIdx.x;
    if (i < n) p[i] = v;
}

__global__ void k_copy_f(float* dst, const float* __restrict__ src, int n) {
    int i = blockIdx.x * blockDim.x + threadIdx.x;
    if (i < n) dst[i] = src[i];
}

// ------------------------- CSR build ----------------------------------------
__global__ void k_count(const int* __restrict__ d, const int* mptr, int fixedM,
                        int* cnt) {
    int m = mptr ? *mptr : fixedM;
    int i = blockIdx.x * blockDim.x + threadIdx.x;
    if (i < m) atomicAdd(&cnt[d[i]], 1);
}

__global__ void k_exscan(const int* __restrict__ in, int* out, int n) {
    __shared__ int sh[1024];
    __shared__ int carry;
    int t = threadIdx.x;
    if (t == 0) carry = 0;
    __syncthreads();
    for (int base = 0; base < n; base += 1024) {
        int idx = base + t;
        int v = (idx < n) ? in[idx] : 0;
        sh[t] = v;
        __syncthreads();
        for (int o = 1; o < 1024; o <<= 1) {
            int tv = (t >= o) ? sh[t - o] : 0;
            __syncthreads();
            sh[t] += tv;
            __syncthreads();
        }
        if (idx < n) out[idx] = carry + sh[t] - v;  // exclusive
        int tot = sh[1023];
        __syncthreads();
        if (t == 0) carry += tot;
        __syncthreads();
    }
    if (t == 0) out[n] = carry;
}

__global__ void k_scatter(const int* __restrict__ s, const int* __restrict__ d,
                          const int* mptr, int fixedM,
                          const int* __restrict__ rp, int* cur, int* esrc) {
    int m = mptr ? *mptr : fixedM;
    int i = blockIdx.x * blockDim.x + threadIdx.x;
    if (i >= m) return;
    int dd = d[i];
    int pos = rp[dd] + atomicAdd(&cur[dd], 1);
    esrc[pos] = s[i];
}

__global__ void k_relabel(const int* __restrict__ ps, const int* __restrict__ pd,
                          const int* mptr, int fixedM,
                          const int* __restrict__ map,
                          int* os, int* od, int* om) {
    int m = mptr ? *mptr : fixedM;
    int i = blockIdx.x * blockDim.x + threadIdx.x;
    if (i >= m) return;
    int a = map[ps[i]], b = map[pd[i]];
    if (a >= 0 && b >= 0) {
        int p = atomicAdd(om, 1);
        os[p] = a; od[p] = b;
    }
}

// ------------------------- max aggregation (CSR, no atomics) -----------------
__global__ void k_aggmax32(const int* __restrict__ rp, const int* __restrict__ es,
                           const float* __restrict__ x, float* agg, int n) {
    int warp = (blockIdx.x * blockDim.x + threadIdx.x) >> 5;
    int lane = threadIdx.x & 31;
    if (warp >= n) return;
    int s = rp[warp], e = rp[warp + 1];
    float m = -INFINITY;
    for (int t = s; t < e; t++)
        m = fmaxf(m, x[(size_t)es[t] * CIN + lane]);
    agg[(size_t)warp * CIN + lane] = (e > s) ? m : 0.0f;
}

__global__ void k_aggmax256(const int* __restrict__ rp, const int* __restrict__ es,
                            const float* __restrict__ x, float* agg, int n) {
    int warp = (blockIdx.x * blockDim.x + threadIdx.x) >> 5;
    int lane = threadIdx.x & 31;
    if (warp >= n) return;
    int s = rp[warp], e = rp[warp + 1];
    float m[8];
#pragma unroll
    for (int j = 0; j < 8; j++) m[j] = -INFINITY;
    for (int t = s; t < e; t++) {
        const float* xr = x + (size_t)es[t] * CH + lane;
#pragma unroll
        for (int j = 0; j < 8; j++) m[j] = fmaxf(m[j], xr[j * 32]);
    }
    float* ar = agg + (size_t)warp * CH + lane;
    bool has = (e > s);
#pragma unroll
    for (int j = 0; j < 8; j++) ar[j * 32] = has ? m[j] : 0.0f;
}

// ------------------------- GEMM (out cols fixed = 256) -----------------------
// C[n,256] (+= / =) A[n,K] @ B[K,256] (+bias) (relu)
__global__ void k_gemm(const float* __restrict__ A, const float* __restrict__ B,
                       const float* __restrict__ bias, const float* Cin,
                       float* C, int n, int K, int relu) {
    __shared__ __align__(16) float As[16][64];
    __shared__ __align__(16) float Bs[16][64];
    int bm = blockIdx.x * 64, bn = blockIdx.y * 64;
    int tid = threadIdx.x;
    int tx = tid & 15, ty = tid >> 4;
    float acc[4][4];
#pragma unroll
    for (int i = 0; i < 4; i++)
#pragma unroll
        for (int j = 0; j < 4; j++) acc[i][j] = 0.f;
    int aRow = tid >> 2, aCol = (tid & 3) * 4;
    int bRow = tid >> 4, bCol = (tid & 15) * 4;
    for (int k0 = 0; k0 < K; k0 += 16) {
        float4 av = make_float4(0.f, 0.f, 0.f, 0.f);
        if (bm + aRow < n)
            av = *(const float4*)(A + (size_t)(bm + aRow) * K + k0 + aCol);
        As[aCol + 0][aRow] = av.x; As[aCol + 1][aRow] = av.y;
        As[aCol + 2][aRow] = av.z; As[aCol + 3][aRow] = av.w;
        *(float4*)(&Bs[bRow][bCol]) =
            *(const float4*)(B + (size_t)(k0 + bRow) * CH + bn + bCol);
        __syncthreads();
#pragma unroll
        for (int kk = 0; kk < 16; kk++) {
            float4 a = *(const float4*)(&As[kk][ty * 4]);
            float4 b = *(const float4*)(&Bs[kk][tx * 4]);
            acc[0][0] += a.x * b.x; acc[0][1] += a.x * b.y;
            acc[0][2] += a.x * b.z; acc[0][3] += a.x * b.w;
            acc[1][0] += a.y * b.x; acc[1][1] += a.y * b.y;
            acc[1][2] += a.y * b.z; acc[1][3] += a.y * b.w;
            acc[2][0] += a.z * b.x; acc[2][1] += a.z * b.y;
            acc[2][2] += a.z * b.z; acc[2][3] += a.z * b.w;
            acc[3][0] += a.w * b.x; acc[3][1] += a.w * b.y;
            acc[3][2] += a.w * b.z; acc[3][3] += a.w * b.w;
        }
        __syncthreads();
    }
#pragma unroll
    for (int i = 0; i < 4; i++) {
        int row = bm + ty * 4 + i;
        if (row >= n) continue;
#pragma unroll
        for (int j = 0; j < 4; j++) {
            int col = bn + tx * 4 + j;
            float v = acc[i][j];
            if (bias) v += bias[col];
            if (Cin)  v += Cin[(size_t)row * CH + col];
            if (relu) v = fmaxf(v, 0.f);
            C[(size_t)row * CH + col] = v;
        }
    }
}

// ------------------------- TopK pooling --------------------------------------
__global__ void k_wnorm(const float* __restrict__ w) {
    __shared__ float sh[256];
    int t = threadIdx.x;
    float v = w[t];
    sh[t] = v * v;
    __syncthreads();
    for (int o = 128; o > 0; o >>= 1) {
        if (t < o) sh[t] += sh[t + o];
        __syncthreads();
    }
    if (t == 0) g_wnorm = sqrtf(sh[0]);
}

__global__ void k_scorekey(const float* __restrict__ x, const float* __restrict__ w,
                           float* score, u64* keys, int n, int P) {
    int gw = (blockIdx.x * blockDim.x + threadIdx.x) >> 5;
    int lane = threadIdx.x & 31;
    if (gw >= P) return;
    if (gw >= n) {
        if (lane == 0) keys[gw] = 0xFFFFFFFFFFFFFFFFull;
        return;
    }
    float p = 0.f;
    const float* xr = x + (size_t)gw * CH;
    for (int c = lane; c < CH; c += 32) p += xr[c] * w[c];
#pragma unroll
    for (int o = 16; o > 0; o >>= 1) p += __shfl_xor_sync(0xffffffffu, p, o);
    if (lane == 0) {
        float s = tanhf(p / g_wnorm);
        score[gw] = s;
        unsigned u = __float_as_uint(s);
        unsigned mono = (u & 0x80000000u) ? ~u : (u | 0x80000000u);
        // ascending sort => descending score, ascending index tie-break
        keys[gw] = ((u64)(~mono) << 32) | (unsigned)gw;
    }
}

__global__ void k_bit_full(u64* keys) {  // all k = 2..2048 inside smem chunks
    __shared__ u64 s[2048];
    int base = blockIdx.x * 2048;
    int t = threadIdx.x;
    s[t] = keys[base + t];
    s[t + 1024] = keys[base + t + 1024];
    __syncthreads();
    for (int k = 2; k <= 2048; k <<= 1) {
        for (int j = k >> 1; j > 0; j >>= 1) {
            int li = ((t & ~(j - 1)) << 1) | (t & (j - 1));
            bool up = (((base + li) & k) == 0);
            u64 a = s[li], b = s[li + j];
            if ((a > b) == up) { s[li] = b; s[li + j] = a; }
            __syncthreads();
        }
    }
    keys[base + t] = s[t];
    keys[base + t + 1024] = s[t + 1024];
}

__global__ void k_bit_smem(u64* keys, int k) {  // j = 1024..1 for a given k
    __shared__ u64 s[2048];
    int base = blockIdx.x * 2048;
    int t = threadIdx.x;
    s[t] = keys[base + t];
    s[t + 1024] = keys[base + t + 1024];
    __syncthreads();
    for (int j = 1024; j > 0; j >>= 1) {
        int li = ((t & ~(j - 1)) << 1) | (t & (j - 1));
        bool up = (((base + li) & k) == 0);
        u64 a = s[li], b = s[li + j];
        if ((a > b) == up) { s[li] = b; s[li + j] = a; }
        __syncthreads();
    }
    keys[base + t] = s[t];
    keys[base + t + 1024] = s[t + 1024];
}

__global__ void k_bit_glob(u64* keys, int j, int k) {
    int i = blockIdx.x * blockDim.x + threadIdx.x;
    int ixj = i ^ j;
    if (ixj > i) {
        bool up = ((i & k) == 0);
        u64 a = keys[i], b = keys[ixj];
        if ((a > b) == up) { keys[i] = b; keys[ixj] = a; }
    }
}

__global__ void k_build(const u64* __restrict__ keys, const float* __restrict__ xin,
                        const float* __restrict__ score, float* xout,
                        int* perm, int* map, int k) {
    int gw = (blockIdx.x * blockDim.x + threadIdx.x) >> 5;
    int lane = threadIdx.x & 31;
    if (gw >= k) return;
    int idx = (int)(keys[gw] & 0xFFFFFFFFull);
    if (lane == 0) { perm[gw] = idx; map[idx] = gw; }
    float v = score[idx];
    const float* xr = xin + (size_t)idx * CH;
    float* xo = xout + (size_t)gw * CH;
    for (int c = lane; c < CH; c += 32) xo[c] = xr[c] * v;
}

// ------------------------- up-path helpers -----------------------------------
__global__ void k_scatadd(float* xu, const float* __restrict__ deep,
                          const int* __restrict__ perm, int k) {
    int i = blockIdx.x * blockDim.x + threadIdx.x;
    if (i >= k * CH) return;
    int r = i >> 8, c = i & 255;
    xu[(size_t)perm[r] * CH + c] += deep[i];
}

// ------------------------- final conv (M=3) + tanh*0.5 -----------------------
__global__ void k_final(const float* __restrict__ agg, const float* __restrict__ x,
                        const float* __restrict__ wl, const float* __restrict__ wr,
                        const float* __restrict__ b, float* out, int n) {
    __shared__ float swl[CH * 3], swr[CH * 3], sb[3];
    for (int i = threadIdx.x; i < CH * 3; i += blockDim.x) {
        swl[i] = wl[i];
        swr[i] = wr[i];
    }
    if (threadIdx.x < 3) sb[threadIdx.x] = b[threadIdx.x];
    __syncthreads();
    int node = blockIdx.x * blockDim.x + threadIdx.x;
    if (node >= n) return;
    float a0 = sb[0], a1 = sb[1], a2 = sb[2];
    const float* ar = agg + (size_t)node * CH;
    const float* xr = x + (size_t)node * CH;
#pragma unroll 4
    for (int c = 0; c < CH; c++) {
        float av = ar[c], xv = xr[c];
        a0 += av * swl[c * 3 + 0] + xv * swr[c * 3 + 0];
        a1 += av * swl[c * 3 + 1] + xv * swr[c * 3 + 1];
        a2 += av * swl[c * 3 + 2] + xv * swr[c * 3 + 2];
    }
    out[node * 3 + 0] = tanhf(a0) * 0.5f;
    out[node * 3 + 1] = tanhf(a1) * 0.5f;
    out[node * 3 + 2] = tanhf(a2) * 0.5f;
}

// ------------------------- host orchestration --------------------------------
static inline int cdiv(int a, int b) { return (a + b - 1) / b; }

template <class T>
static void* gp(const T& sym) {
    void* p = nullptr;
    cudaGetSymbolAddress(&p, sym);
    return p;
}

extern "C" void kernel_launch(void* const* d_in, const int* in_sizes, int n_in,
                              void* d_out, int out_size) {
    const float* x_in = (const float*)d_in[0];
    const unsigned* eidx = (const unsigned*)d_in[1];
    const float* w0l  = (const float*)d_in[2];
    const float* w0r  = (const float*)d_in[3];
    const float* b0   = (const float*)d_in[4];
    const float* dwl  = (const float*)d_in[5];
    const float* dwr  = (const float*)d_in[6];
    const float* db   = (const float*)d_in[7];
    const float* poolw = (const float*)d_in[8];
    const float* uwl  = (const float*)d_in[9];
    const float* uwr  = (const float*)d_in[10];
    const float* ub   = (const float*)d_in[11];
    const float* uwlL = (const float*)d_in[12];
    const float* uwrL = (const float*)d_in[13];
    const float* ubL  = (const float*)d_in[14];
    float* out = (float*)d_out;

    int*   srcP  = (int*)gp(g_src);
    int*   dstP  = (int*)gp(g_dst);
    int*   e1sP  = (int*)gp(g_e1s); int* e1dP = (int*)gp(g_e1d);
    int*   e2sP  = (int*)gp(g_e2s); int* e2dP = (int*)gp(g_e2d);
    int*   e3sP  = (int*)gp(g_e3s); int* e3dP = (int*)gp(g_e3d);
    int*   es0P  = (int*)gp(g_es0); int* es1P = (int*)gp(g_es1);
    int*   es2P  = (int*)gp(g_es2); int* es3P = (int*)gp(g_es3);
    int*   rp0P  = (int*)gp(g_rp0); int* rp1P = (int*)gp(g_rp1);
    int*   rp2P  = (int*)gp(g_rp2); int* rp3P = (int*)gp(g_rp3);
    int*   cntP  = (int*)gp(g_cnt);
    int*   m1P   = (int*)gp(g_m1);
    int*   m2P   = (int*)gp(g_m2);
    int*   m3P   = (int*)gp(g_m3);
    int*   mapP  = (int*)gp(g_map);
    int*   p1P   = (int*)gp(g_perm1);
    int*   p2P   = (int*)gp(g_perm2);
    int*   p3P   = (int*)gp(g_perm3);
    float* h0P   = (float*)gp(g_h0);
    float* h1P   = (float*)gp(g_h1);
    float* h2P   = (float*)gp(g_h2);
    float* h3P   = (float*)gp(g_h3);
    float* xaP   = (float*)gp(g_xa);
    float* xbP   = (float*)gp(g_xb);
    float* aggP  = (float*)gp(g_agg);
    float* scoreP = (float*)gp(g_score);
    u64*   keysP = (u64*)gp(g_keys);

    const int EG = cdiv(NE, 256);  // edge-sized grids

    auto build_csr = [&](const int* s, const int* d, const int* mptr, int fixedM,
                         int n, int* rp, int* esrc) {
        k_fill_int<<<cdiv(n, 256), 256>>>(cntP, n, 0);
        k_count<<<EG, 256>>>(d, mptr, fixedM, cntP);
        k_exscan<<<1, 1024>>>(cntP, rp, n);
        k_fill_int<<<cdiv(n, 256), 256>>>(cntP, n, 0);
        k_scatter<<<EG, 256>>>(s, d, mptr, fixedM, rp, cntP, esrc);
    };

    auto conv = [&](const float* xin, int n, const int* rp, const int* esrc,
                    const float* wl, const float* wr, const float* bias,
                    float* outb, int relu) {
        k_aggmax256<<<cdiv(n, 8), 256>>>(rp, esrc, xin, aggP, n);
        dim3 g(cdiv(n, 64), 4);
        k_gemm<<<g, 256>>>(aggP, wl, bias, nullptr, outb, n, CH, 0);
        k_gemm<<<g, 256>>>(xin, wr, nullptr, outb, outb, n, CH, relu);
    };

    auto pool = [&](const float* xin, int n, int P, int k, const float* w,
                    int* perm, float* xout) {
        k_wnorm<<<1, 256>>>(w);
        k_scorekey<<<cdiv(P * 32, 256), 256>>>(xin, w, scoreP, keysP, n, P);
        k_bit_full<<<P / 2048, 1024>>>(keysP);
        for (int kk = 4096; kk <= P; kk <<= 1) {
            for (int j = kk >> 1; j >= 2048; j >>= 1)
                k_bit_glob<<<P / 256, 256>>>(keysP, j, kk);
            k_bit_smem<<<P / 2048, 1024>>>(keysP, kk);
        }
        k_fill_int<<<cdiv(n, 256), 256>>>(mapP, n, -1);
        k_build<<<cdiv(k * 32, 256), 256>>>(keysP, xin, scoreP, xout, perm, mapP, k);
    };

    // --- decode edge_index (int32 or int64, device-detected) ---
    k_detect<<<1, 256>>>(eidx);
    k_convert<<<EG, 256>>>(eidx);

    // --- level-0 CSR + first conv (C_IN=32) ---
    build_csr(srcP, dstP, nullptr, NE, N0, rp0P, es0P);
    k_aggmax32<<<cdiv(N0, 8), 256>>>(rp0P, es0P, x_in, aggP, N0);
    {
        dim3 g(cdiv(N0, 64), 4);
        k_gemm<<<g, 256>>>(aggP, w0l, b0, nullptr, h0P, N0, CIN, 0);
        k_gemm<<<g, 256>>>(x_in, w0r, nullptr, h0P, h0P, N0, CIN, 1);
    }

    // --- pool 1 + conv 1 ---
    pool(h0P, N0, PW1, KP1, poolw, p1P, xaP);
    k_fill_int<<<1, 32>>>(m1P, 1, 0);
    k_relabel<<<EG, 256>>>(srcP, dstP, nullptr, NE, mapP, e1sP, e1dP, m1P);
    build_csr(e1sP, e1dP, m1P, 0, KP1, rp1P, es1P);
    conv(xaP, KP1, rp1P, es1P, dwl, dwr, db, h1P, 1);

    // --- pool 2 + conv 2 ---
    pool(h1P, KP1, PW2, KP2, poolw + CH, p2P, xaP);
    k_fill_int<<<1, 32>>>(m2P, 1, 0);
    k_relabel<<<EG, 256>>>(e1sP, e1dP, m1P, 0, mapP, e2sP, e2dP, m2P);
    build_csr(e2sP, e2dP, m2P, 0, KP2, rp2P, es2P);
    conv(xaP, KP2, rp2P, es2P, dwl + CH*CH, dwr + CH*CH, db + CH, h2P, 1);

    // --- pool 3 + conv 3 ---
    pool(h2P, KP2, PW3, KP3, poolw + 2*CH, p3P, xaP);
    k_fill_int<<<1, 32>>>(m3P, 1, 0);
    k_relabel<<<EG, 256>>>(e2sP, e2dP, m2P, 0, mapP, e3sP, e3dP, m3P);
    build_csr(e3sP, e3dP, m3P, 0, KP3, rp3P, es3P);
    conv(xaP, KP3, rp3P, es3P, dwl + 2*CH*CH, dwr + 2*CH*CH, db + 2*CH, h3P, 1);

    // --- up path ---
    // i=0: n=12500, res=h2, perm=p3, deeper=h3, edges=level2
    k_copy_f<<<cdiv(KP2 * CH, 256), 256>>>(xaP, h2P, KP2 * CH);
    k_scatadd<<<cdiv(KP3 * CH, 256), 256>>>(xaP, h3P, p3P, KP3);
    conv(xaP, KP2, rp2P, es2P, uwl, uwr, ub, xbP, 1);

    // i=1: n=25000, res=h1, perm=p2, deeper=xb(12500), edges=level1
    k_copy_f<<<cdiv(KP1 * CH, 256), 256>>>(xaP, h1P, KP1 * CH);
    k_scatadd<<<cdiv(KP2 * CH, 256), 256>>>(xaP, xbP, p2P, KP2);
    conv(xaP, KP1, rp1P, es1P, uwl + CH*CH, uwr + CH*CH, ub + CH, xbP, 1);

    // i=2: n=50000, res=h0, perm=p1, deeper=xb(25000), edges=level0, M=3
    k_copy_f<<<cdiv(N0 * CH, 256), 256>>>(xaP, h0P, N0 * CH);
    k_scatadd<<<cdiv(KP1 * CH, 256), 256>>>(xaP, xbP, p1P, KP1);
    k_aggmax256<<<cdiv(N0, 8), 256>>>(rp0P, es0P, xaP, aggP, N0);
    k_final<<<cdiv(N0, 256), 256>>>(aggP, xaP, uwlL, uwrL, ubL, out, N0);
}